// round 1
// baseline (speedup 1.0000x reference)
#include <cuda_runtime.h>

// Problem constants
#define BB 1024
#define TT 200
#define DD 128
#define HH 128
#define MM (BB*TT)   // 204800

// Scratch for the precomputed x-dependent halves of the matmuls.
// Xg[m][j] = b_gate[j] + sum_k X[m][k]*W_gate[k][j]      (j in [0,256))
// Xc[m][j] = b_cand[j] + sum_k X[m][k]*W_cand[k][j]      (j in [0,128))
__device__ float g_Xg[(size_t)MM * 256];
__device__ float g_Xc[(size_t)MM * 128];

__device__ __forceinline__ float sigmoid_f(float x) {
    return __fdividef(1.0f, 1.0f + __expf(-x));
}
__device__ __forceinline__ float tanh_f(float x) {
    // exact at +-inf saturation: exp overflow -> 1, underflow -> -1
    return 1.0f - __fdividef(2.0f, __expf(2.0f * x) + 1.0f);
}

// ---------------------------------------------------------------------------
// Kernel A: Xg/Xc precompute GEMM. Block tile 128(M) x 128(N), K=128 (whole).
// grid = (1600, 3): nt=0,1 -> gate cols [0,128),[128,256); nt=2 -> cand cols.
// 256 threads, each computes an 8x8 register tile.
// ---------------------------------------------------------------------------
__global__ __launch_bounds__(256, 1)
void precompute_kernel(const float* __restrict__ X,
                       const float* __restrict__ Wg,
                       const float* __restrict__ bg,
                       const float* __restrict__ Wc,
                       const float* __restrict__ bc)
{
    extern __shared__ float sm[];
    float* Xs = sm;               // [128][132] row-major, padded
    float* Ws = sm + 128 * 132;   // [128][128]

    const int mt = blockIdx.x;
    const int nt = blockIdx.y;
    const int m0 = mt * 128;
    const int tid = threadIdx.x;

    // Load X tile (128x128 f32) coalesced, row-major into padded smem.
    #pragma unroll
    for (int i = 0; i < 16; i++) {
        int idx = tid + i * 256;        // float4 index 0..4095
        int m   = idx >> 5;             // 0..127
        int k4  = idx & 31;             // 0..31
        float4 v = *(const float4*)&X[(size_t)(m0 + m) * 128 + k4 * 4];
        *(float4*)&Xs[m * 132 + k4 * 4] = v;
    }
    // Load weight tile (x-part rows 0..127).
    {
        const float* Wsrc; int ldw, n0;
        if (nt < 2) { Wsrc = Wg; ldw = 256; n0 = nt * 128; }
        else        { Wsrc = Wc; ldw = 128; n0 = 0; }
        #pragma unroll
        for (int i = 0; i < 16; i++) {
            int idx = tid + i * 256;
            int k   = idx >> 5;
            int j4  = idx & 31;
            float4 v = *(const float4*)&Wsrc[(size_t)k * ldw + n0 + j4 * 4];
            *(float4*)&Ws[k * 128 + j4 * 4] = v;
        }
    }
    __syncthreads();

    const int colg = tid & 15;          // 16 col groups of 8
    const int rowg = tid >> 4;          // 16 row groups of 8
    const int c0 = colg * 8;
    const int r0 = rowg * 8;

    float acc[8][8];
    #pragma unroll
    for (int i = 0; i < 8; i++)
        #pragma unroll
        for (int j = 0; j < 8; j++) acc[i][j] = 0.0f;

    #pragma unroll 4
    for (int k = 0; k < 128; k++) {
        float4 w0 = *(const float4*)&Ws[k * 128 + c0];
        float4 w1 = *(const float4*)&Ws[k * 128 + c0 + 4];
        float wv[8] = {w0.x, w0.y, w0.z, w0.w, w1.x, w1.y, w1.z, w1.w};
        float xv[8];
        #pragma unroll
        for (int i = 0; i < 8; i++) xv[i] = Xs[(r0 + i) * 132 + k];
        #pragma unroll
        for (int i = 0; i < 8; i++)
            #pragma unroll
            for (int j = 0; j < 8; j++)
                acc[i][j] = fmaf(xv[i], wv[j], acc[i][j]);
    }

    if (nt < 2) {
        const int n0 = nt * 128;
        float4 bv0 = *(const float4*)&bg[n0 + c0];
        float4 bv1 = *(const float4*)&bg[n0 + c0 + 4];
        #pragma unroll
        for (int i = 0; i < 8; i++) {
            float4 o0, o1;
            o0.x = acc[i][0] + bv0.x; o0.y = acc[i][1] + bv0.y;
            o0.z = acc[i][2] + bv0.z; o0.w = acc[i][3] + bv0.w;
            o1.x = acc[i][4] + bv1.x; o1.y = acc[i][5] + bv1.y;
            o1.z = acc[i][6] + bv1.z; o1.w = acc[i][7] + bv1.w;
            size_t base = (size_t)(m0 + r0 + i) * 256 + n0 + c0;
            *(float4*)&g_Xg[base]     = o0;
            *(float4*)&g_Xg[base + 4] = o1;
        }
    } else {
        float4 bv0 = *(const float4*)&bc[c0];
        float4 bv1 = *(const float4*)&bc[c0 + 4];
        #pragma unroll
        for (int i = 0; i < 8; i++) {
            float4 o0, o1;
            o0.x = acc[i][0] + bv0.x; o0.y = acc[i][1] + bv0.y;
            o0.z = acc[i][2] + bv0.z; o0.w = acc[i][3] + bv0.w;
            o1.x = acc[i][4] + bv1.x; o1.y = acc[i][5] + bv1.y;
            o1.z = acc[i][6] + bv1.z; o1.w = acc[i][7] + bv1.w;
            size_t base = (size_t)(m0 + r0 + i) * 128 + c0;
            *(float4*)&g_Xc[base]     = o0;
            *(float4*)&g_Xc[base + 4] = o1;
        }
    }
}

// ---------------------------------------------------------------------------
// Kernel B: the GRU recurrence. Each block owns 8 batch rows for all T steps.
// Recurrent weights (h-part, 192KB) live in SMEM for the whole kernel.
// 128 blocks x 128 threads.
// Phase G: thread tile 4 rows x 4 gate cols  (c0 = (tid&63)*4,  r0 = (tid>>6)*4)
// Phase C: thread tile 4 rows x 2 cand cols  (cc0 = (tid&63)*2, same r0)
// ---------------------------------------------------------------------------
__global__ __launch_bounds__(128, 1)
void gru_kernel(const float* __restrict__ Wg,   // [256][256]
                const float* __restrict__ Wc,   // [256][128]
                const int*   __restrict__ seq_len,
                float* __restrict__ out)        // [1024][200][128]
{
    extern __shared__ float sm[];
    float* Wg_s = sm;                      // [128][256] (h-part of W_gate)
    float* Wc_s = Wg_s + 128 * 256;        // [128][128] (h-part of W_cand)
    float* h_s  = Wc_s + 128 * 128;        // [8][132]
    float* rh_s = h_s  + 8 * 132;          // [8][132]
    float* u_s  = rh_s + 8 * 132;          // [8][132]

    const int tid = threadIdx.x;
    const int b0  = blockIdx.x * 8;

    // Load recurrent weights once.
    #pragma unroll
    for (int i = 0; i < 64; i++) {         // 32768 floats
        int idx = tid + i * 128;
        *(float4*)&Wg_s[idx * 4] = *(const float4*)&Wg[128 * 256 + idx * 4];
    }
    #pragma unroll
    for (int i = 0; i < 32; i++) {         // 16384 floats
        int idx = tid + i * 128;
        *(float4*)&Wc_s[idx * 4] = *(const float4*)&Wc[128 * 128 + idx * 4];
    }
    for (int i = tid; i < 8 * 132; i += 128) h_s[i] = 0.0f;
    __syncthreads();

    const int colg = tid & 63;
    const int rowg = tid >> 6;
    const int c0   = colg * 4;             // gate col base: 0..252
    const int cc0  = colg * 2;             // cand col base: 0..126
    const int r0   = rowg * 4;             // row base: 0 or 4

    int sl[4];
    #pragma unroll
    for (int i = 0; i < 4; i++) sl[i] = seq_len[b0 + r0 + i];

    for (int t = 0; t < TT; t++) {
        // ---------------- Phase G: gates = sigmoid(xg + h @ Wg_h) ----------
        float4 xg[4];
        #pragma unroll
        for (int i = 0; i < 4; i++)
            xg[i] = *(const float4*)&g_Xg[((size_t)(b0 + r0 + i) * TT + t) * 256 + c0];

        float acc[4][4];
        #pragma unroll
        for (int i = 0; i < 4; i++)
            #pragma unroll
            for (int j = 0; j < 4; j++) acc[i][j] = 0.0f;

        #pragma unroll 8
        for (int k = 0; k < 128; k++) {
            float4 w = *(const float4*)&Wg_s[k * 256 + c0];
            float h0 = h_s[(r0 + 0) * 132 + k];
            float h1 = h_s[(r0 + 1) * 132 + k];
            float h2 = h_s[(r0 + 2) * 132 + k];
            float h3 = h_s[(r0 + 3) * 132 + k];
            acc[0][0] = fmaf(h0, w.x, acc[0][0]); acc[0][1] = fmaf(h0, w.y, acc[0][1]);
            acc[0][2] = fmaf(h0, w.z, acc[0][2]); acc[0][3] = fmaf(h0, w.w, acc[0][3]);
            acc[1][0] = fmaf(h1, w.x, acc[1][0]); acc[1][1] = fmaf(h1, w.y, acc[1][1]);
            acc[1][2] = fmaf(h1, w.z, acc[1][2]); acc[1][3] = fmaf(h1, w.w, acc[1][3]);
            acc[2][0] = fmaf(h2, w.x, acc[2][0]); acc[2][1] = fmaf(h2, w.y, acc[2][1]);
            acc[2][2] = fmaf(h2, w.z, acc[2][2]); acc[2][3] = fmaf(h2, w.w, acc[2][3]);
            acc[3][0] = fmaf(h3, w.x, acc[3][0]); acc[3][1] = fmaf(h3, w.y, acc[3][1]);
            acc[3][2] = fmaf(h3, w.z, acc[3][2]); acc[3][3] = fmaf(h3, w.w, acc[3][3]);
        }

        #pragma unroll
        for (int i = 0; i < 4; i++) {
            float4 g;
            g.x = sigmoid_f(acc[i][0] + xg[i].x);
            g.y = sigmoid_f(acc[i][1] + xg[i].y);
            g.z = sigmoid_f(acc[i][2] + xg[i].z);
            g.w = sigmoid_f(acc[i][3] + xg[i].w);
            if (c0 < 128) {
                // r-gate: store r*h (transparent for cand phase)
                float4 h4 = *(const float4*)&h_s[(r0 + i) * 132 + c0];
                float4 rh;
                rh.x = g.x * h4.x; rh.y = g.y * h4.y;
                rh.z = g.z * h4.z; rh.w = g.w * h4.w;
                *(float4*)&rh_s[(r0 + i) * 132 + c0] = rh;
            } else {
                // u-gate
                *(float4*)&u_s[(r0 + i) * 132 + (c0 - 128)] = g;
            }
        }
        __syncthreads();

        // ---------------- Phase C: c = tanh(xc + (r*h) @ Wc_h); h update ---
        float2 xc[4];
        #pragma unroll
        for (int i = 0; i < 4; i++)
            xc[i] = *(const float2*)&g_Xc[((size_t)(b0 + r0 + i) * TT + t) * 128 + cc0];

        float acc2[4][2];
        #pragma unroll
        for (int i = 0; i < 4; i++) { acc2[i][0] = 0.0f; acc2[i][1] = 0.0f; }

        #pragma unroll 8
        for (int k = 0; k < 128; k++) {
            float2 w = *(const float2*)&Wc_s[k * 128 + cc0];
            float p0 = rh_s[(r0 + 0) * 132 + k];
            float p1 = rh_s[(r0 + 1) * 132 + k];
            float p2 = rh_s[(r0 + 2) * 132 + k];
            float p3 = rh_s[(r0 + 3) * 132 + k];
            acc2[0][0] = fmaf(p0, w.x, acc2[0][0]); acc2[0][1] = fmaf(p0, w.y, acc2[0][1]);
            acc2[1][0] = fmaf(p1, w.x, acc2[1][0]); acc2[1][1] = fmaf(p1, w.y, acc2[1][1]);
            acc2[2][0] = fmaf(p2, w.x, acc2[2][0]); acc2[2][1] = fmaf(p2, w.y, acc2[2][1]);
            acc2[3][0] = fmaf(p3, w.x, acc2[3][0]); acc2[3][1] = fmaf(p3, w.y, acc2[3][1]);
        }

        #pragma unroll
        for (int i = 0; i < 4; i++) {
            float cv0 = tanh_f(acc2[i][0] + xc[i].x);
            float cv1 = tanh_f(acc2[i][1] + xc[i].y);
            float2 hh = *(const float2*)&h_s[(r0 + i) * 132 + cc0];
            float2 uu = *(const float2*)&u_s[(r0 + i) * 132 + cc0];
            float hn0 = uu.x * hh.x + (1.0f - uu.x) * cv0;
            float hn1 = uu.y * hh.y + (1.0f - uu.y) * cv1;
            bool valid = (t < sl[i]);
            float2 hw, yw;
            hw.x = valid ? hn0 : hh.x;   hw.y = valid ? hn1 : hh.y;
            yw.x = valid ? hn0 : 0.0f;   yw.y = valid ? hn1 : 0.0f;
            *(float2*)&h_s[(r0 + i) * 132 + cc0] = hw;
            *(float2*)&out[((size_t)(b0 + r0 + i) * TT + t) * 128 + cc0] = yw;
        }
        __syncthreads();
    }
}

// ---------------------------------------------------------------------------
extern "C" void kernel_launch(void* const* d_in, const int* in_sizes, int n_in,
                              void* d_out, int out_size)
{
    (void)in_sizes; (void)n_in; (void)out_size;
    const float* X   = (const float*)d_in[0];   // item_his_eb [1024,200,128]
    const int*   sq  = (const int*)  d_in[1];   // seq_len [1024]
    const float* Wg  = (const float*)d_in[2];   // W_gate [256,256]
    const float* bg  = (const float*)d_in[3];   // b_gate [256]
    const float* Wc  = (const float*)d_in[4];   // W_cand [256,128]
    const float* bc  = (const float*)d_in[5];   // b_cand [128]
    float* out = (float*)d_out;                 // [1024,200,128]

    const int smemA = (128 * 132 + 128 * 128) * 4;                    // 133120
    const int smemB = (128 * 256 + 128 * 128 + 3 * 8 * 132) * 4;      // 209280
    cudaFuncSetAttribute(precompute_kernel,
                         cudaFuncAttributeMaxDynamicSharedMemorySize, smemA);
    cudaFuncSetAttribute(gru_kernel,
                         cudaFuncAttributeMaxDynamicSharedMemorySize, smemB);

    precompute_kernel<<<dim3(1600, 3, 1), 256, smemA>>>(X, Wg, bg, Wc, bc);
    gru_kernel<<<128, 128, smemB>>>(Wg, Wc, sq, out);
}